// round 2
// baseline (speedup 1.0000x reference)
#include <cuda_runtime.h>
#include <cuda_bf16.h>

// Embedding gather: out[row, :] = w[x[row], :]
// x: [8, 2048] int32 (16384 indices), w: [50257, 1024] fp32, out: [16384, 1024] fp32
//
// One block per output row. 256 threads * float4 = 1024 floats = one full row.
// All loads/stores are 128-bit, fully coalesced along the row.

#define EMB_DIM 1024
#define VEC_PER_ROW (EMB_DIM / 4)   // 256 float4 per row

__global__ void __launch_bounds__(256, 8) embedding_gather_kernel(
    const int* __restrict__ x,
    const float4* __restrict__ w,
    float4* __restrict__ out,
    int n_rows)
{
    int row = blockIdx.x;
    if (row >= n_rows) return;

    int idx = __ldg(&x[row]);               // uniform broadcast within block
    const float4* src = w + (long long)idx * VEC_PER_ROW;
    float4* dst = out + (long long)row * VEC_PER_ROW;

    int c = threadIdx.x;                    // 0..255, one float4 each
    dst[c] = src[c];
}

extern "C" void kernel_launch(void* const* d_in, const int* in_sizes, int n_in,
                              void* d_out, int out_size) {
    const int*    x = (const int*)d_in[0];          // [8*2048] indices
    const float4* w = (const float4*)d_in[1];       // [50257*1024] fp32 as float4
    float4*       o = (float4*)d_out;

    int n_rows = in_sizes[0];                       // 16384
    embedding_gather_kernel<<<n_rows, 256>>>(x, w, o, n_rows);
}

// round 4
// speedup vs baseline: 1.7127x; 1.7127x over previous
#include <cuda_runtime.h>
#include <cuda_bf16.h>

// Embedding gather: out[row, :] = w[x[row], :]
// x: [16384] int32, w: [50257, 1024] fp32, out: [16384, 1024] fp32
//
// 4 rows per block, 256 threads. Each thread owns one float4 column slot and
// processes it for all 4 rows: 4 independent front-batched LDG.128 (MLP=4),
// then 4 streaming STG.128 (evict-first: writes have no reuse, keep the
// gathered w-rows in L2 for duplicate indices).

#define EMB_DIM 1024
#define VEC_PER_ROW (EMB_DIM / 4)   // 256 float4 per row
#define ROWS_PER_BLOCK 4

__device__ __forceinline__ void stcs_f4(float4* p, float4 v) {
    asm volatile("st.global.cs.v4.f32 [%0], {%1,%2,%3,%4};"
                 :: "l"(p), "f"(v.x), "f"(v.y), "f"(v.z), "f"(v.w) : "memory");
}

__global__ void __launch_bounds__(256, 8) embedding_gather_kernel(
    const int* __restrict__ x,
    const float4* __restrict__ w,
    float4* __restrict__ out,
    int n_rows)
{
    int row0 = blockIdx.x * ROWS_PER_BLOCK;
    int c = threadIdx.x;                       // column slot 0..255

    // Uniform index loads (broadcast within block, L1-resident)
    int idx0 = __ldg(&x[row0 + 0]);
    int idx1 = __ldg(&x[row0 + 1]);
    int idx2 = __ldg(&x[row0 + 2]);
    int idx3 = __ldg(&x[row0 + 3]);

    // Front-batched independent gathers: MLP = 4
    float4 v0 = w[(long long)idx0 * VEC_PER_ROW + c];
    float4 v1 = w[(long long)idx1 * VEC_PER_ROW + c];
    float4 v2 = w[(long long)idx2 * VEC_PER_ROW + c];
    float4 v3 = w[(long long)idx3 * VEC_PER_ROW + c];

    float4* dst = out + (long long)row0 * VEC_PER_ROW + c;
    stcs_f4(dst + 0 * VEC_PER_ROW, v0);
    stcs_f4(dst + 1 * VEC_PER_ROW, v1);
    stcs_f4(dst + 2 * VEC_PER_ROW, v2);
    stcs_f4(dst + 3 * VEC_PER_ROW, v3);
}

extern "C" void kernel_launch(void* const* d_in, const int* in_sizes, int n_in,
                              void* d_out, int out_size) {
    const int*    x = (const int*)d_in[0];          // [16384] indices
    const float4* w = (const float4*)d_in[1];       // [50257*1024] fp32 as float4
    float4*       o = (float4*)d_out;

    int n_rows = in_sizes[0];                       // 16384
    int n_blocks = n_rows / ROWS_PER_BLOCK;         // 4096
    embedding_gather_kernel<<<n_blocks, 256>>>(x, w, o, n_rows);
}